// round 16
// baseline (speedup 1.0000x reference)
#include <cuda_runtime.h>
#include <cuda_fp16.h>
#include <math.h>
#include <stdint.h>

// Problem constants
#define T_TOK 2048
#define DIM   1024
#define DFS   2048
#define DFE   512
#define NE    8
#define KMAX  8

#define NTH   256      // threads per GEMM CTA (8 warps)
#define KT    64       // K chunk
#define SMS   144      // smem row stride bytes (64 fp16 + 8 pad)

// ---------------- static device scratch ----------------
__device__ __half Xh[T_TOK * DIM],  Xl[T_TOK * DIM];   // x hi/lo
__device__ __half SGh[DFS * DIM];                      // shared weights, hi only (B side)
__device__ __half SUh[DFS * DIM];
__device__ __half SDh[DIM * DFS];
__device__ __half EG[NE * DFE * DIM];                  // exact int-valued fp16
__device__ __half EU[NE * DFE * DIM];
__device__ __half ED[NE * DIM * DFE];
__device__ __half HSh[T_TOK * DFS], HSl[T_TOK * DFS];  // shared hidden hi/lo (A side)
__device__ __half HEh[T_TOK * KMAX * DFE], HEl[T_TOK * KMAX * DFE];
__device__ float g_eo[T_TOK * KMAX * DIM];
__device__ int   g_cnt[NE];
__device__ int   g_pair[NE * T_TOK];
__device__ float g_wt[NE * T_TOK];
__device__ float g_ss[T_TOK];

// ---------------- PTX helpers ----------------
__device__ __forceinline__ uint32_t smem_u32(const void* p) {
    uint32_t a;
    asm("{ .reg .u64 t; cvta.to.shared.u64 t, %1; cvt.u32.u64 %0, t; }" : "=r"(a) : "l"(p));
    return a;
}
__device__ __forceinline__ void ldsm4(uint32_t* r, uint32_t addr) {
    asm volatile("ldmatrix.sync.aligned.m8n8.x4.shared.b16 {%0,%1,%2,%3}, [%4];"
        : "=r"(r[0]), "=r"(r[1]), "=r"(r[2]), "=r"(r[3]) : "r"(addr));
}
__device__ __forceinline__ void mma_f16(float* c, const uint32_t* a, const uint32_t* b) {
    asm volatile("mma.sync.aligned.m16n8k16.row.col.f32.f16.f16.f32 "
        "{%0,%1,%2,%3}, {%4,%5,%6,%7}, {%8,%9}, {%0,%1,%2,%3};"
        : "+f"(c[0]), "+f"(c[1]), "+f"(c[2]), "+f"(c[3])
        : "r"(a[0]), "r"(a[1]), "r"(a[2]), "r"(a[3]), "r"(b[0]), "r"(b[1]));
}
__device__ __forceinline__ void split_h(float v, __half& h, __half& l) {
    h = __float2half(v);
    l = __float2half(v - __half2float(h));
}
__device__ __forceinline__ float silu_mul(float g, float u) {
    return g / (1.f + expf(-g)) * u;
}

// ---------------- small kernels ----------------
__global__ void k_zero() { if (threadIdx.x < NE) g_cnt[threadIdx.x] = 0; }

__global__ __launch_bounds__(256) void k_router(
    const float* __restrict__ x, const float* __restrict__ rw,
    const float* __restrict__ alpha, const int* __restrict__ topkp)
{
    const int warp = threadIdx.x >> 5, lane = threadIdx.x & 31;
    const int t = blockIdx.x * (blockDim.x >> 5) + warp;
    if (t >= T_TOK) return;
    float xv[32];
    const float* xr = x + t * DIM;
#pragma unroll
    for (int i = 0; i < 32; i++) xv[i] = xr[lane + (i << 5)];
    float lg[NE];
#pragma unroll
    for (int e = 0; e < NE; e++) {
        const float* r = rw + e * DIM;
        float acc = 0.f;
#pragma unroll
        for (int i = 0; i < 32; i++) acc = fmaf(xv[i], r[lane + (i << 5)], acc);
#pragma unroll
        for (int o = 16; o > 0; o >>= 1) acc += __shfl_xor_sync(0xffffffffu, acc, o);
        lg[e] = acc;
    }
    if (lane == 0) {
        int k = *topkp; if (k > NE) k = NE; if (k < 1) k = 1;
        int idx[KMAX]; float val[KMAX]; unsigned used = 0;
        for (int j = 0; j < k; j++) {
            int bi = 0; float bv = -INFINITY;
            for (int e = 0; e < NE; e++)
                if (!((used >> e) & 1u) && lg[e] > bv) { bv = lg[e]; bi = e; }
            used |= 1u << bi; idx[j] = bi; val[j] = bv;
        }
        float m = val[0], s = 0.f;
        for (int j = 0; j < k; j++) { val[j] = expf(val[j] - m); s += val[j]; }
        const float inv = 1.f / s;
        float ssum = 0.f;
        for (int j = 0; j < k; j++) {
            const float a = val[j] * inv * alpha[idx[j]];
            ssum += a;
            const int pos = atomicAdd(&g_cnt[idx[j]], 1);
            g_pair[idx[j] * T_TOK + pos] = t * KMAX + j;
            g_wt[idx[j] * T_TOK + pos]   = a;
        }
        g_ss[t] = 1.f - ssum;
    }
}

// x -> hi/lo fp16
__global__ void k_cvt_x(const float* __restrict__ x) {
    int i = blockIdx.x * blockDim.x + threadIdx.x;
    const int st = gridDim.x * blockDim.x;
    for (; i < T_TOK * DIM; i += st) {
        __half h, l; split_h(x[i], h, l); Xh[i] = h; Xl[i] = l;
    }
}
// shared weights -> single fp16 (all three same element count)
__global__ void k_cvt_w(const float* __restrict__ sg, const float* __restrict__ su,
                        const float* __restrict__ sd) {
    int i = blockIdx.x * blockDim.x + threadIdx.x;
    const int st = gridDim.x * blockDim.x;
    for (; i < DFS * DIM; i += st) {
        SGh[i] = __float2half(sg[i]);
        SUh[i] = __float2half(su[i]);
        SDh[i] = __float2half(sd[i]);
    }
}
// expert int weights -> exact fp16 (all three 4M elements)
__global__ void k_dq(const int* __restrict__ gq, const int* __restrict__ uq,
                     const int* __restrict__ dq) {
    int i = blockIdx.x * blockDim.x + threadIdx.x;
    const int st = gridDim.x * blockDim.x;
    for (; i < NE * DFE * DIM; i += st) {
        EG[i] = __int2half_rn(gq[i]);
        EU[i] = __int2half_rn(uq[i]);
        ED[i] = __int2half_rn(dq[i]);
    }
}

// ---------------- mma.sync fp16 GEMM engine (A hi/lo split, B single) ----------------
// CTA tile 128x64 (per B matrix), 8 warps as 4(M) x 2(N), warp tile 32x32.
// Double-buffered smem, one __syncthreads per K chunk.
// MODE 0: shared gate+up (A=X h/l,  B=SGh/SUh, K=1024) -> HS h/l
// MODE 1: shared down    (A=HS h/l, B=SDh,     K=2048) -> out*g_ss
// MODE 2: expert gate+up (A=X gath, B=EG/EU,   K=1024, col scales) -> HE h/l
// MODE 3: expert down    (A=HE gath, B=ED,     K=512,  col scales) -> g_eo
template <int MODE>
__global__ __launch_bounds__(NTH) void k_gemm(
    float* __restrict__ out, const float* __restrict__ sc0, const float* __restrict__ sc1)
{
    constexpr bool DUAL = (MODE == 0 || MODE == 2);
    constexpr bool GATH = (MODE == 2 || MODE == 3);
    constexpr int  K    = (MODE == 1) ? 2048 : (MODE == 3 ? 512 : 1024);
    constexpr int  NCH  = K / KT;
    constexpr int  NMAT = DUAL ? 2 : 1;
    constexpr int  NB   = DUAL ? 4 : 2;     // B uint4 per thread per chunk
    constexpr int  S_B  = 2 * 128 * SMS;    // A region: Ah[128]+Al[128]
    constexpr int  BSEC = 64 * SMS;
    constexpr int  BUFSZ = S_B + NMAT * BSEC;

    extern __shared__ __align__(16) char sm[];
    const uint32_t sb = smem_u32(sm);

    const int tid = threadIdx.x, wid = tid >> 5, lid = tid & 31;
    const int wm = wid & 3, wn = wid >> 2;
    const int e = GATH ? blockIdx.z : 0;
    int cnt = T_TOK;
    if (GATH) { cnt = g_cnt[e]; if ((int)(blockIdx.y << 7) >= cnt) return; }
    const int m0 = blockIdx.y << 7;
    const int n0 = blockIdx.x << 6;

    // ---- A producer: 1 row per thread (amat: 0=hi, 1=lo), 8 uint4 per chunk ----
    const int amat = tid >> 7, arow = tid & 127;
    const __half* Asrc;
    if (MODE == 0)      Asrc = (amat ? Xl  : Xh)  + (m0 + arow) * DIM;
    else if (MODE == 1) Asrc = (amat ? HSl : HSh) + (m0 + arow) * DFS;
    else {
        int r = m0 + arow; if (r > cnt - 1) r = cnt - 1;
        const int pr = g_pair[e * T_TOK + r];
        if (MODE == 2) Asrc = (amat ? Xl  : Xh)  + (pr >> 3) * DIM;
        else           Asrc = (amat ? HEl : HEh) + pr * DFE;
    }
    const uint32_t smA = amat * 128 * SMS + arow * SMS;

    // ---- B producer ----
    int bsec, brow, bseg;
    const __half* Bsrc;
    if (DUAL) {
        bsec = tid >> 7; brow = (tid >> 1) & 63; bseg = (tid & 1) * 4;
        if (MODE == 0) Bsrc = (bsec ? SUh : SGh) + (n0 + brow) * DIM;
        else           Bsrc = (bsec ? EU  : EG)  + e * DFE * DIM + (n0 + brow) * DIM;
    } else {
        bsec = 0; brow = tid >> 2; bseg = (tid & 3) * 2;
        if (MODE == 1) Bsrc = SDh + (n0 + brow) * DFS;
        else           Bsrc = ED  + e * DIM * DFE + (n0 + brow) * DFE;
    }
    const uint32_t smB = S_B + bsec * BSEC + brow * SMS + bseg * 16;

    // ---- consumer bases ----
    const uint32_t aBase = sb + (wm * 32 + (lid & 15)) * SMS + (lid >> 4) * 16;
    const int bn_off = ((lid >> 4) & 1) * 8 + (lid & 7);
    const int bk_off = ((lid >> 3) & 1) * 16;
    const uint32_t bBase = sb + S_B + (wn * 32 + bn_off) * SMS + bk_off;

    float acc0[32] = {};
    float acc1[32] = {};
    uint4 rA[8], rB[NB];

    auto LOAD = [&](int c) {
        const int k0 = c * KT;
#pragma unroll
        for (int j = 0; j < 8; j++) rA[j] = *(const uint4*)(Asrc + k0 + j * 8);
#pragma unroll
        for (int j = 0; j < NB; j++) rB[j] = *(const uint4*)(Bsrc + k0 + (bseg + j) * 8);
    };
    auto STORE = [&](int buf) {
        char* bp = sm + buf * BUFSZ;
#pragma unroll
        for (int j = 0; j < 8; j++)  *(uint4*)(bp + smA + j * 16) = rA[j];
#pragma unroll
        for (int j = 0; j < NB; j++) *(uint4*)(bp + smB + j * 16) = rB[j];
    };
    auto MMAP = [&](int buf) {
        const uint32_t bo = buf * BUFSZ;
#pragma unroll
        for (int ks = 0; ks < 4; ks++) {
            uint32_t aH[2][4], aL[2][4];
#pragma unroll
            for (int mt = 0; mt < 2; mt++) {
                ldsm4(aH[mt], aBase + bo + mt * 16 * SMS + ks * 32);
                ldsm4(aL[mt], aBase + bo + 128 * SMS + mt * 16 * SMS + ks * 32);
            }
#pragma unroll
            for (int mat = 0; mat < NMAT; mat++) {
                uint32_t bH[2][4];
#pragma unroll
                for (int p = 0; p < 2; p++)
                    ldsm4(bH[p], bBase + bo + mat * BSEC + p * 16 * SMS + ks * 32);
                float* accm = (mat == 0) ? acc0 : acc1;
#pragma unroll
                for (int mt = 0; mt < 2; mt++)
#pragma unroll
                    for (int p = 0; p < 2; p++)
#pragma unroll
                        for (int s = 0; s < 2; s++) {
                            float* cc = &accm[(mt * 4 + p * 2 + s) * 4];
                            mma_f16(cc, aH[mt], &bH[p][s * 2]);
                            mma_f16(cc, aL[mt], &bH[p][s * 2]);
                        }
            }
        }
    };

    // ---- pipelined mainloop ----
    LOAD(0);
    STORE(0);
    __syncthreads();
#pragma unroll 1
    for (int c = 0; c < NCH; c++) {
        const bool more = (c + 1 < NCH);
        if (more) LOAD(c + 1);          // gmem latency hides under MMA phase
        MMAP(c & 1);
        if (more) {
            STORE((c + 1) & 1);         // opposite buffer: no conflict with MMA reads
            __syncthreads();
        }
    }

    // ---- epilogue ----
    const int l4 = lid >> 2, l2 = (lid & 3) << 1;
#pragma unroll
    for (int mt = 0; mt < 2; mt++)
#pragma unroll
        for (int nt = 0; nt < 4; nt++) {
            const float* cg = &acc0[(mt * 4 + nt) * 4];
            const float* cu = &acc1[(mt * 4 + nt) * 4];
            const int colb = n0 + wn * 32 + nt * 8 + l2;
#pragma unroll
            for (int h = 0; h < 2; h++) {
                const int mrow = m0 + wm * 32 + mt * 16 + l4 + h * 8;
                const float r0 = cg[h * 2], r1 = cg[h * 2 + 1];
                if (MODE == 0) {
                    const float v0 = silu_mul(r0, cu[h * 2]);
                    const float v1 = silu_mul(r1, cu[h * 2 + 1]);
                    __half h0, l0, h1, l1;
                    split_h(v0, h0, l0); split_h(v1, h1, l1);
                    const int ob = mrow * DFS + colb;
                    *(__half2*)(HSh + ob) = __halves2half2(h0, h1);
                    *(__half2*)(HSl + ob) = __halves2half2(l0, l1);
                } else if (MODE == 1) {
                    const float s = g_ss[mrow];
                    *(float2*)(out + mrow * DIM + colb) = make_float2(s * r0, s * r1);
                } else if (MODE == 2) {
                    if (mrow < cnt) {
                        const int pr = g_pair[e * T_TOK + mrow];
                        const float gs0 = sc0[e * DFE + colb], gs1 = sc0[e * DFE + colb + 1];
                        const float us0 = sc1[e * DFE + colb], us1 = sc1[e * DFE + colb + 1];
                        const float v0 = silu_mul(r0 * gs0, cu[h * 2] * us0);
                        const float v1 = silu_mul(r1 * gs1, cu[h * 2 + 1] * us1);
                        __half h0, l0, h1, l1;
                        split_h(v0, h0, l0); split_h(v1, h1, l1);
                        const int ob = pr * DFE + colb;
                        *(__half2*)(HEh + ob) = __halves2half2(h0, h1);
                        *(__half2*)(HEl + ob) = __halves2half2(l0, l1);
                    }
                } else {
                    if (mrow < cnt) {
                        const int pr = g_pair[e * T_TOK + mrow];
                        const float w = g_wt[e * T_TOK + mrow];
                        const float d0 = sc0[e * DIM + colb], d1 = sc0[e * DIM + colb + 1];
                        *(float2*)(g_eo + pr * DIM + colb) =
                            make_float2(w * d0 * r0, w * d1 * r1);
                    }
                }
            }
        }
}

// ---------------- final combine ----------------
__global__ void k_combine(float* __restrict__ out, const int* __restrict__ topkp)
{
    int k = *topkp; if (k > KMAX) k = KMAX; if (k < 1) k = 1;
    const int i = blockIdx.x * blockDim.x + threadIdx.x;
    if (i >= T_TOK * DIM) return;
    const int t = i >> 10, d = i & (DIM - 1);
    float acc = out[i];
    for (int j = 0; j < k; j++) acc += g_eo[(t * KMAX + j) * DIM + d];
    out[i] = acc;
}

// ---------------- host launcher ----------------
extern "C" void kernel_launch(void* const* d_in, const int* in_sizes, int n_in,
                              void* d_out, int out_size)
{
    const float* x     = (const float*)d_in[0];
    const float* rw    = (const float*)d_in[1];
    const float* sgw   = (const float*)d_in[2];
    const float* suw   = (const float*)d_in[3];
    const float* sdw   = (const float*)d_in[4];
    const float* gs    = (const float*)d_in[5];
    const float* us    = (const float*)d_in[6];
    const float* ds    = (const float*)d_in[7];
    const float* alpha = (const float*)d_in[8];
    const int*   gq    = (const int*)d_in[9];
    const int*   uq    = (const int*)d_in[10];
    const int*   dq    = (const int*)d_in[11];
    const int*   topk  = (const int*)d_in[12];
    float* out = (float*)d_out;

    // double-buffered smem: 2 * (A(2x128) + NMAT*64 rows) * SMS
    const int SM_DUAL   = 2 * (2 * 128 * SMS + 2 * 64 * SMS);  // 110592
    const int SM_SINGLE = 2 * (2 * 128 * SMS + 1 * 64 * SMS);  // 92160
    cudaFuncSetAttribute(k_gemm<0>, cudaFuncAttributeMaxDynamicSharedMemorySize, SM_DUAL);
    cudaFuncSetAttribute(k_gemm<1>, cudaFuncAttributeMaxDynamicSharedMemorySize, SM_SINGLE);
    cudaFuncSetAttribute(k_gemm<2>, cudaFuncAttributeMaxDynamicSharedMemorySize, SM_DUAL);
    cudaFuncSetAttribute(k_gemm<3>, cudaFuncAttributeMaxDynamicSharedMemorySize, SM_SINGLE);

    k_zero<<<1, 32>>>();
    k_router<<<T_TOK / 8, 256>>>(x, rw, alpha, topk);

    k_cvt_x<<<2048, 256>>>(x);
    k_cvt_w<<<2048, 256>>>(sgw, suw, sdw);
    k_dq<<<2048, 256>>>(gq, uq, dq);

    k_gemm<0><<<dim3(DFS / 64, T_TOK / 128),     NTH, SM_DUAL>>>(nullptr, nullptr, nullptr);
    k_gemm<1><<<dim3(DIM / 64, T_TOK / 128),     NTH, SM_SINGLE>>>(out, nullptr, nullptr);
    k_gemm<2><<<dim3(DFE / 64, T_TOK / 128, NE), NTH, SM_DUAL>>>(nullptr, gs, us);
    k_gemm<3><<<dim3(DIM / 64, T_TOK / 128, NE), NTH, SM_SINGLE>>>(nullptr, ds, nullptr);

    k_combine<<<(T_TOK * DIM + 255) / 256, 256>>>(out, topk);
}

// round 17
// speedup vs baseline: 1.7865x; 1.7865x over previous
#include <cuda_runtime.h>
#include <cuda_fp16.h>
#include <math.h>
#include <stdint.h>

// Problem constants
#define T_TOK 2048
#define DIM   1024
#define DFS   2048
#define DFE   512
#define NE    8
#define KMAX  8

#define NTH   256      // threads per GEMM CTA (8 warps)
#define KT    64       // K chunk
#define SMS   144      // smem row stride bytes (64 fp16 + 8 pad)

// ---------------- static device scratch ----------------
__device__ __half Xh[T_TOK * DIM];                     // x fp16
__device__ __half SGh[DFS * DIM];                      // shared weights fp16
__device__ __half SUh[DFS * DIM];
__device__ __half SDh[DIM * DFS];
__device__ __half EG[NE * DFE * DIM];                  // exact int-valued fp16
__device__ __half EU[NE * DFE * DIM];
__device__ __half ED[NE * DIM * DFE];
__device__ __half HSh[T_TOK * DFS];                    // shared hidden fp16
__device__ __half HEh[T_TOK * KMAX * DFE];             // expert hidden fp16
__device__ float g_eo[T_TOK * KMAX * DIM];
__device__ int   g_cnt[NE];
__device__ int   g_pair[NE * T_TOK];
__device__ float g_wt[NE * T_TOK];
__device__ float g_ss[T_TOK];

// ---------------- PTX helpers ----------------
__device__ __forceinline__ uint32_t smem_u32(const void* p) {
    uint32_t a;
    asm("{ .reg .u64 t; cvta.to.shared.u64 t, %1; cvt.u32.u64 %0, t; }" : "=r"(a) : "l"(p));
    return a;
}
__device__ __forceinline__ void ldsm4(uint32_t* r, uint32_t addr) {
    asm volatile("ldmatrix.sync.aligned.m8n8.x4.shared.b16 {%0,%1,%2,%3}, [%4];"
        : "=r"(r[0]), "=r"(r[1]), "=r"(r[2]), "=r"(r[3]) : "r"(addr));
}
__device__ __forceinline__ void mma_f16(float* c, const uint32_t* a, const uint32_t* b) {
    asm volatile("mma.sync.aligned.m16n8k16.row.col.f32.f16.f16.f32 "
        "{%0,%1,%2,%3}, {%4,%5,%6,%7}, {%8,%9}, {%0,%1,%2,%3};"
        : "+f"(c[0]), "+f"(c[1]), "+f"(c[2]), "+f"(c[3])
        : "r"(a[0]), "r"(a[1]), "r"(a[2]), "r"(a[3]), "r"(b[0]), "r"(b[1]));
}
__device__ __forceinline__ float silu_mul(float g, float u) {
    return g / (1.f + expf(-g)) * u;
}

// ---------------- small kernels ----------------
__global__ void k_zero() { if (threadIdx.x < NE) g_cnt[threadIdx.x] = 0; }

__global__ __launch_bounds__(256) void k_router(
    const float* __restrict__ x, const float* __restrict__ rw,
    const float* __restrict__ alpha, const int* __restrict__ topkp)
{
    const int warp = threadIdx.x >> 5, lane = threadIdx.x & 31;
    const int t = blockIdx.x * (blockDim.x >> 5) + warp;
    if (t >= T_TOK) return;
    float xv[32];
    const float* xr = x + t * DIM;
#pragma unroll
    for (int i = 0; i < 32; i++) xv[i] = xr[lane + (i << 5)];
    float lg[NE];
#pragma unroll
    for (int e = 0; e < NE; e++) {
        const float* r = rw + e * DIM;
        float acc = 0.f;
#pragma unroll
        for (int i = 0; i < 32; i++) acc = fmaf(xv[i], r[lane + (i << 5)], acc);
#pragma unroll
        for (int o = 16; o > 0; o >>= 1) acc += __shfl_xor_sync(0xffffffffu, acc, o);
        lg[e] = acc;
    }
    if (lane == 0) {
        int k = *topkp; if (k > NE) k = NE; if (k < 1) k = 1;
        int idx[KMAX]; float val[KMAX]; unsigned used = 0;
        for (int j = 0; j < k; j++) {
            int bi = 0; float bv = -INFINITY;
            for (int e = 0; e < NE; e++)
                if (!((used >> e) & 1u) && lg[e] > bv) { bv = lg[e]; bi = e; }
            used |= 1u << bi; idx[j] = bi; val[j] = bv;
        }
        float m = val[0], s = 0.f;
        for (int j = 0; j < k; j++) { val[j] = expf(val[j] - m); s += val[j]; }
        const float inv = 1.f / s;
        float ssum = 0.f;
        for (int j = 0; j < k; j++) {
            const float a = val[j] * inv * alpha[idx[j]];
            ssum += a;
            const int pos = atomicAdd(&g_cnt[idx[j]], 1);
            g_pair[idx[j] * T_TOK + pos] = t * KMAX + j;
            g_wt[idx[j] * T_TOK + pos]   = a;
        }
        g_ss[t] = 1.f - ssum;
    }
}

// x -> fp16
__global__ void k_cvt_x(const float* __restrict__ x) {
    int i = blockIdx.x * blockDim.x + threadIdx.x;
    const int st = gridDim.x * blockDim.x;
    for (; i < T_TOK * DIM; i += st) Xh[i] = __float2half(x[i]);
}
// shared weights -> fp16 (all three same element count)
__global__ void k_cvt_w(const float* __restrict__ sg, const float* __restrict__ su,
                        const float* __restrict__ sd) {
    int i = blockIdx.x * blockDim.x + threadIdx.x;
    const int st = gridDim.x * blockDim.x;
    for (; i < DFS * DIM; i += st) {
        SGh[i] = __float2half(sg[i]);
        SUh[i] = __float2half(su[i]);
        SDh[i] = __float2half(sd[i]);
    }
}
// expert int weights -> exact fp16 (all three 4M elements)
__global__ void k_dq(const int* __restrict__ gq, const int* __restrict__ uq,
                     const int* __restrict__ dq) {
    int i = blockIdx.x * blockDim.x + threadIdx.x;
    const int st = gridDim.x * blockDim.x;
    for (; i < NE * DFE * DIM; i += st) {
        EG[i] = __int2half_rn(gq[i]);
        EU[i] = __int2half_rn(uq[i]);
        ED[i] = __int2half_rn(dq[i]);
    }
}

// ---------------- mma.sync fp16 GEMM engine (single-term) ----------------
// CTA tile 128x64 (per B matrix), 8 warps as 4(M) x 2(N), warp tile 32x32.
// Double-buffered smem, one __syncthreads per K chunk.
// MODE 0: shared gate+up (A=X,  B=SGh/SUh, K=1024) -> HSh
// MODE 1: shared down    (A=HS, B=SDh,     K=2048) -> out*g_ss
// MODE 2: expert gate+up (A=X gath, B=EG/EU, K=1024, col scales) -> HEh
// MODE 3: expert down    (A=HE gath, B=ED,   K=512,  col scales) -> g_eo
template <int MODE>
__global__ __launch_bounds__(NTH) void k_gemm(
    float* __restrict__ out, const float* __restrict__ sc0, const float* __restrict__ sc1)
{
    constexpr bool DUAL = (MODE == 0 || MODE == 2);
    constexpr bool GATH = (MODE == 2 || MODE == 3);
    constexpr int  K    = (MODE == 1) ? 2048 : (MODE == 3 ? 512 : 1024);
    constexpr int  NCH  = K / KT;
    constexpr int  NMAT = DUAL ? 2 : 1;
    constexpr int  NB   = DUAL ? 4 : 2;     // B uint4 per thread per chunk
    constexpr int  S_B  = 128 * SMS;        // A region: 128 rows
    constexpr int  BSEC = 64 * SMS;
    constexpr int  BUFSZ = S_B + NMAT * BSEC;

    extern __shared__ __align__(16) char sm[];
    const uint32_t sb = smem_u32(sm);

    const int tid = threadIdx.x, wid = tid >> 5, lid = tid & 31;
    const int wm = wid & 3, wn = wid >> 2;
    const int e = GATH ? blockIdx.z : 0;
    int cnt = T_TOK;
    if (GATH) { cnt = g_cnt[e]; if ((int)(blockIdx.y << 7) >= cnt) return; }
    const int m0 = blockIdx.y << 7;
    const int n0 = blockIdx.x << 6;

    // ---- A producer: 128 rows, 1 row per 2 threads, 4 uint4 each ----
    const int arow = tid >> 1, aseg = (tid & 1) * 4;
    const __half* Asrc;
    if (MODE == 0)      Asrc = Xh  + (m0 + arow) * DIM;
    else if (MODE == 1) Asrc = HSh + (m0 + arow) * DFS;
    else {
        int r = m0 + arow; if (r > cnt - 1) r = cnt - 1;
        const int pr = g_pair[e * T_TOK + r];
        if (MODE == 2) Asrc = Xh  + (pr >> 3) * DIM;
        else           Asrc = HEh + pr * DFE;
    }
    const uint32_t smA = arow * SMS + aseg * 16;

    // ---- B producer ----
    int bsec, brow, bseg;
    const __half* Bsrc;
    if (DUAL) {
        bsec = tid >> 7; brow = (tid >> 1) & 63; bseg = (tid & 1) * 4;
        if (MODE == 0) Bsrc = (bsec ? SUh : SGh) + (n0 + brow) * DIM;
        else           Bsrc = (bsec ? EU  : EG)  + e * DFE * DIM + (n0 + brow) * DIM;
    } else {
        bsec = 0; brow = tid >> 2; bseg = (tid & 3) * 2;
        if (MODE == 1) Bsrc = SDh + (n0 + brow) * DFS;
        else           Bsrc = ED  + e * DIM * DFE + (n0 + brow) * DFE;
    }
    const uint32_t smB = S_B + bsec * BSEC + brow * SMS + bseg * 16;

    // ---- consumer bases ----
    const uint32_t aBase = sb + (wm * 32 + (lid & 15)) * SMS + (lid >> 4) * 16;
    const int bn_off = ((lid >> 4) & 1) * 8 + (lid & 7);
    const int bk_off = ((lid >> 3) & 1) * 16;
    const uint32_t bBase = sb + S_B + (wn * 32 + bn_off) * SMS + bk_off;

    float acc0[32] = {};
    float acc1[32] = {};
    uint4 rA[4], rB[NB];

    auto LOAD = [&](int c) {
        const int k0 = c * KT;
#pragma unroll
        for (int j = 0; j < 4; j++) rA[j] = *(const uint4*)(Asrc + k0 + (aseg + j) * 8);
#pragma unroll
        for (int j = 0; j < NB; j++) rB[j] = *(const uint4*)(Bsrc + k0 + (bseg + j) * 8);
    };
    auto STORE = [&](int buf) {
        char* bp = sm + buf * BUFSZ;
#pragma unroll
        for (int j = 0; j < 4; j++)  *(uint4*)(bp + smA + j * 16) = rA[j];
#pragma unroll
        for (int j = 0; j < NB; j++) *(uint4*)(bp + smB + j * 16) = rB[j];
    };
    auto MMAP = [&](int buf) {
        const uint32_t bo = buf * BUFSZ;
#pragma unroll
        for (int ks = 0; ks < 4; ks++) {
            uint32_t aH[2][4];
#pragma unroll
            for (int mt = 0; mt < 2; mt++)
                ldsm4(aH[mt], aBase + bo + mt * 16 * SMS + ks * 32);
#pragma unroll
            for (int mat = 0; mat < NMAT; mat++) {
                uint32_t bH[2][4];
#pragma unroll
                for (int p = 0; p < 2; p++)
                    ldsm4(bH[p], bBase + bo + mat * BSEC + p * 16 * SMS + ks * 32);
                float* accm = (mat == 0) ? acc0 : acc1;
#pragma unroll
                for (int mt = 0; mt < 2; mt++)
#pragma unroll
                    for (int p = 0; p < 2; p++)
#pragma unroll
                        for (int s = 0; s < 2; s++)
                            mma_f16(&accm[(mt * 4 + p * 2 + s) * 4], aH[mt], &bH[p][s * 2]);
            }
        }
    };

    // ---- pipelined mainloop ----
    LOAD(0);
    STORE(0);
    __syncthreads();
#pragma unroll 1
    for (int c = 0; c < NCH; c++) {
        const bool more = (c + 1 < NCH);
        if (more) LOAD(c + 1);          // gmem latency hides under MMA phase
        MMAP(c & 1);
        if (more) {
            STORE((c + 1) & 1);         // opposite buffer: no conflict with MMA reads
            __syncthreads();
        }
    }

    // ---- epilogue ----
    const int l4 = lid >> 2, l2 = (lid & 3) << 1;
#pragma unroll
    for (int mt = 0; mt < 2; mt++)
#pragma unroll
        for (int nt = 0; nt < 4; nt++) {
            const float* cg = &acc0[(mt * 4 + nt) * 4];
            const float* cu = &acc1[(mt * 4 + nt) * 4];
            const int colb = n0 + wn * 32 + nt * 8 + l2;
#pragma unroll
            for (int h = 0; h < 2; h++) {
                const int mrow = m0 + wm * 32 + mt * 16 + l4 + h * 8;
                const float r0 = cg[h * 2], r1 = cg[h * 2 + 1];
                if (MODE == 0) {
                    const float v0 = silu_mul(r0, cu[h * 2]);
                    const float v1 = silu_mul(r1, cu[h * 2 + 1]);
                    *(__half2*)(HSh + mrow * DFS + colb) =
                        __halves2half2(__float2half(v0), __float2half(v1));
                } else if (MODE == 1) {
                    const float s = g_ss[mrow];
                    *(float2*)(out + mrow * DIM + colb) = make_float2(s * r0, s * r1);
                } else if (MODE == 2) {
                    if (mrow < cnt) {
                        const int pr = g_pair[e * T_TOK + mrow];
                        const float gs0 = sc0[e * DFE + colb], gs1 = sc0[e * DFE + colb + 1];
                        const float us0 = sc1[e * DFE + colb], us1 = sc1[e * DFE + colb + 1];
                        const float v0 = silu_mul(r0 * gs0, cu[h * 2] * us0);
                        const float v1 = silu_mul(r1 * gs1, cu[h * 2 + 1] * us1);
                        *(__half2*)(HEh + pr * DFE + colb) =
                            __halves2half2(__float2half(v0), __float2half(v1));
                    }
                } else {
                    if (mrow < cnt) {
                        const int pr = g_pair[e * T_TOK + mrow];
                        const float w = g_wt[e * T_TOK + mrow];
                        const float d0 = sc0[e * DIM + colb], d1 = sc0[e * DIM + colb + 1];
                        *(float2*)(g_eo + pr * DIM + colb) =
                            make_float2(w * d0 * r0, w * d1 * r1);
                    }
                }
            }
        }
}

// ---------------- final combine ----------------
__global__ void k_combine(float* __restrict__ out, const int* __restrict__ topkp)
{
    int k = *topkp; if (k > KMAX) k = KMAX; if (k < 1) k = 1;
    const int i = blockIdx.x * blockDim.x + threadIdx.x;
    if (i >= T_TOK * DIM) return;
    const int t = i >> 10, d = i & (DIM - 1);
    float acc = out[i];
    for (int j = 0; j < k; j++) acc += g_eo[(t * KMAX + j) * DIM + d];
    out[i] = acc;
}

// ---------------- host launcher ----------------
extern "C" void kernel_launch(void* const* d_in, const int* in_sizes, int n_in,
                              void* d_out, int out_size)
{
    const float* x     = (const float*)d_in[0];
    const float* rw    = (const float*)d_in[1];
    const float* sgw   = (const float*)d_in[2];
    const float* suw   = (const float*)d_in[3];
    const float* sdw   = (const float*)d_in[4];
    const float* gs    = (const float*)d_in[5];
    const float* us    = (const float*)d_in[6];
    const float* ds    = (const float*)d_in[7];
    const float* alpha = (const float*)d_in[8];
    const int*   gq    = (const int*)d_in[9];
    const int*   uq    = (const int*)d_in[10];
    const int*   dq    = (const int*)d_in[11];
    const int*   topk  = (const int*)d_in[12];
    float* out = (float*)d_out;

    // double-buffered smem: 2 * (A(128) + NMAT*64 rows) * SMS
    const int SM_DUAL   = 2 * (128 * SMS + 2 * 64 * SMS);  // 73728
    const int SM_SINGLE = 2 * (128 * SMS + 1 * 64 * SMS);  // 55296
    cudaFuncSetAttribute(k_gemm<0>, cudaFuncAttributeMaxDynamicSharedMemorySize, SM_DUAL);
    cudaFuncSetAttribute(k_gemm<1>, cudaFuncAttributeMaxDynamicSharedMemorySize, SM_SINGLE);
    cudaFuncSetAttribute(k_gemm<2>, cudaFuncAttributeMaxDynamicSharedMemorySize, SM_DUAL);
    cudaFuncSetAttribute(k_gemm<3>, cudaFuncAttributeMaxDynamicSharedMemorySize, SM_SINGLE);

    k_zero<<<1, 32>>>();
    k_router<<<T_TOK / 8, 256>>>(x, rw, alpha, topk);

    k_cvt_x<<<2048, 256>>>(x);
    k_cvt_w<<<2048, 256>>>(sgw, suw, sdw);
    k_dq<<<2048, 256>>>(gq, uq, dq);

    k_gemm<0><<<dim3(DFS / 64, T_TOK / 128),     NTH, SM_DUAL>>>(nullptr, nullptr, nullptr);
    k_gemm<1><<<dim3(DIM / 64, T_TOK / 128),     NTH, SM_SINGLE>>>(out, nullptr, nullptr);
    k_gemm<2><<<dim3(DFE / 64, T_TOK / 128, NE), NTH, SM_DUAL>>>(nullptr, gs, us);
    k_gemm<3><<<dim3(DIM / 64, T_TOK / 128, NE), NTH, SM_SINGLE>>>(nullptr, ds, nullptr);

    k_combine<<<(T_TOK * DIM + 255) / 256, 256>>>(out, topk);
}